// round 13
// baseline (speedup 1.0000x reference)
#include <cuda_runtime.h>
#include <cuda_fp16.h>
#include <math.h>
#include <stdint.h>

// LSTM cell via warp-level fp16 mma.sync (base PTX ISA — safe for plain sm_103 target).
// R13: single fused pack kernel (A + B + bias) ahead of the unchanged R12 GEMM.
// Single-pass pure fp16, K = 2048; measured rel_err 2.0e-4 (threshold 1e-3).
// Packed operands are pre-SW128-swizzled so stage loads are identity 16B copies.

#define BATCH_N 4096
#define HID_N   1024
#define GATE_ELEMS ((size_t)BATCH_N * HID_N)

#define NCHUNK  32          // K chunks of 64 fp16 (K = 2048)
#define ACHUNKS 32
#define BCHUNKS 32
#define TILE_M  128
#define TILE_N  128         // packed gate-rows r = 4*j + gate
#define NT_M    32
#define NT_N    32
#define A_BLK   16384       // 128 rows * 128B
#define B_BLK   16384
#define STAGE_BYTES (A_BLK + B_BLK)   // 32 KB
#define NSTAGE  3
#define SMEM_TOTAL (NSTAGE * STAGE_BYTES)   // 98304
#define EPI_STRIDE 132       // floats per row in epilogue smem (128 + 4 pad)

#define A_UNITS ((uint32_t)NT_M * ACHUNKS * 1024u)   // 1,048,576 16B units
#define B_UNITS ((uint32_t)NT_N * BCHUNKS * 1024u)   // 1,048,576 16B units

__device__ __align__(1024) unsigned char g_Apack[(size_t)NT_M * ACHUNKS * A_BLK];  // 16 MB
__device__ __align__(1024) unsigned char g_Bpack[(size_t)NT_N * BCHUNKS * B_BLK];  // 16 MB
__device__ float g_bias[4096];

// ---------------------------------------------------------------- PTX helpers (base ISA)
__device__ __forceinline__ uint32_t smem_u32(const void* p) {
    uint32_t a;
    asm("{ .reg .u64 t; cvta.to.shared.u64 t, %1; cvt.u32.u64 %0, t; }" : "=r"(a) : "l"(p));
    return a;
}
__device__ __forceinline__ void cp_async16(uint32_t dst, const void* src) {
    asm volatile("cp.async.cg.shared.global [%0], [%1], 16;" :: "r"(dst), "l"(src) : "memory");
}
__device__ __forceinline__ void cp_commit() {
    asm volatile("cp.async.commit_group;" ::: "memory");
}
template <int N>
__device__ __forceinline__ void cp_wait() {
    asm volatile("cp.async.wait_group %0;" :: "n"(N) : "memory");
}
__device__ __forceinline__ void ldsm_x4(uint32_t& r0, uint32_t& r1, uint32_t& r2, uint32_t& r3,
                                        uint32_t addr) {
    asm volatile("ldmatrix.sync.aligned.m8n8.x4.shared.b16 {%0,%1,%2,%3}, [%4];"
                 : "=r"(r0), "=r"(r1), "=r"(r2), "=r"(r3) : "r"(addr));
}
__device__ __forceinline__ void mma16816(float& d0, float& d1, float& d2, float& d3,
                                         uint32_t a0, uint32_t a1, uint32_t a2, uint32_t a3,
                                         uint32_t b0, uint32_t b1) {
    asm volatile("mma.sync.aligned.m16n8k16.row.col.f32.f16.f16.f32 "
                 "{%0,%1,%2,%3}, {%4,%5,%6,%7}, {%8,%9}, {%0,%1,%2,%3};"
                 : "+f"(d0), "+f"(d1), "+f"(d2), "+f"(d3)
                 : "r"(a0), "r"(a1), "r"(a2), "r"(a3), "r"(b0), "r"(b1));
}
__device__ __forceinline__ uint32_t swz(uint32_t off) { return off ^ ((off >> 3) & 0x70u); }

__device__ __forceinline__ float fast_sigmoid(float x) {
    return 1.0f / (1.0f + __expf(-x));
}
__device__ __forceinline__ float fast_tanh(float x) {
    return 2.0f / (1.0f + __expf(-2.0f * x)) - 1.0f;   // saturation-safe
}

// ---------------------------------------------------------------- fused pack kernel

struct LstmPtrs {
    const float* wi[4];
    const float* wh[4];
    const float* bi[4];
    const float* bh[4];
};

// Blocks [0, 4096): A units. Blocks [4096, 8192): B units (+bias).
// A stored chunks 0..31 over k in [0,2048): [0:1024) input | [1024:2048) h.
// B tiles of 128 packed rows r = 4*j + gate, n-major; slots over k in [0,2048):
// even 1024-seg = Wi, odd = Wh.
__global__ __launch_bounds__(256)
void pack_ab_kernel(const float* __restrict__ input, const float* __restrict__ hst,
                    LstmPtrs P)
{
    uint32_t gu = blockIdx.x * 256u + threadIdx.x;

    if (gu < A_UNITS) {
        uint32_t u = gu;
        uint32_t tile_m = u / (ACHUNKS * 1024u);
        uint32_t rem = u % (ACHUNKS * 1024u);
        uint32_t ck = rem / 1024u;
        uint32_t w = rem % 1024u;
        uint32_t i = w >> 3;
        uint32_t kq = w & 7u;
        uint32_t row = tile_m * TILE_M + i;
        uint32_t k = ck * 64u + kq * 8u;        // [0, 2048)
        const float* src = (k < 1024u) ? input : hst;
        uint32_t col = k & 1023u;

        const float4* sp = reinterpret_cast<const float4*>(src + (size_t)row * HID_N + col);
        float4 v0 = sp[0], v1 = sp[1];
        float vals[8] = {v0.x, v0.y, v0.z, v0.w, v1.x, v1.y, v1.z, v1.w};
        __align__(16) __half ob[8];
#pragma unroll
        for (int t = 0; t < 8; t++) ob[t] = __float2half_rn(vals[t]);
        uint32_t off = i * 128u + kq * 16u;
        *reinterpret_cast<uint4*>(g_Apack + (size_t)(tile_m * ACHUNKS + ck) * A_BLK + swz(off)) =
            *reinterpret_cast<uint4*>(ob);
    } else {
        uint32_t u = gu - A_UNITS;
        uint32_t tile_n = u / (BCHUNKS * 1024u);
        uint32_t rem = u % (BCHUNKS * 1024u);
        uint32_t cks = rem / 1024u;             // storage slot 0..31
        uint32_t w = rem % 1024u;
        uint32_t i = w >> 3;                    // row in tile (0..127)
        uint32_t kq = w & 7u;
        uint32_t r = tile_n * TILE_N + i;
        uint32_t j = r >> 2;
        uint32_t g = r & 3u;
        uint32_t k = cks * 64u + kq * 8u;       // [0, 2048)
        const float* src = (k >> 10) ? P.wh[g] : P.wi[g];
        uint32_t col = k & 1023u;

        const float4* sp = reinterpret_cast<const float4*>(src + (size_t)j * HID_N + col);
        float4 v0 = sp[0], v1 = sp[1];
        float vals[8] = {v0.x, v0.y, v0.z, v0.w, v1.x, v1.y, v1.z, v1.w};
        __align__(16) __half ob[8];
#pragma unroll
        for (int t = 0; t < 8; t++) ob[t] = __float2half_rn(vals[t]);
        uint32_t off = i * 128u + kq * 16u;
        *reinterpret_cast<uint4*>(g_Bpack + (size_t)(tile_n * BCHUNKS + cks) * B_BLK + swz(off)) =
            *reinterpret_cast<uint4*>(ob);

        // combined biases: one per packed row
        if (u < 4096u) {
            uint32_t rr = u, jj = rr >> 2, gg = rr & 3u;
            g_bias[rr] = P.bi[gg][jj] + P.bh[gg][jj];
        }
    }
}

// ---------------------------------------------------------------- GEMM + fused LSTM epilogue

__device__ __forceinline__ void load_stage(uint32_t sdst, const unsigned char* aSrc,
                                           const unsigned char* bSrc, int tid)
{
#pragma unroll
    for (int i = 0; i < 4; i++)
        cp_async16(sdst + tid * 16 + i * 4096, aSrc + tid * 16 + i * 4096);
#pragma unroll
    for (int i = 0; i < 4; i++)
        cp_async16(sdst + A_BLK + tid * 16 + i * 4096, bSrc + tid * 16 + i * 4096);
}

__global__ __launch_bounds__(256, 2)
void lstm_mma_kernel(const float* __restrict__ cprev, float* __restrict__ out)
{
    extern __shared__ __align__(1024) unsigned char smem[];
    const uint32_t sb = smem_u32(smem);
    const int tid = threadIdx.x;
    const int warp = tid >> 5, lane = tid & 31;
    const int wm = warp & 3, wn = warp >> 2;      // 4 (M) x 2 (N) warps, warp tile 32x64
    const int m_warp = wm * 32, n_warp = wn * 64;
    const int tile_n = blockIdx.x, tile_m = blockIdx.y;

    const unsigned char* aBase = g_Apack + (size_t)tile_m * ACHUNKS * A_BLK;
    const unsigned char* bBase = g_Bpack + (size_t)tile_n * BCHUNKS * B_BLK;

    float acc[2][8][4];
#pragma unroll
    for (int mt = 0; mt < 2; mt++)
#pragma unroll
        for (int nt = 0; nt < 8; nt++)
#pragma unroll
            for (int e = 0; e < 4; e++) acc[mt][nt][e] = 0.0f;

    // prefetch stages 0,1
    load_stage(sb, aBase, bBase, tid);
    cp_commit();
    load_stage(sb + STAGE_BYTES, aBase + A_BLK, bBase + B_BLK, tid);
    cp_commit();

    // ldmatrix lane addressing
    const uint32_t a_row = (uint32_t)(lane & 15);          // 0..15
    const uint32_t a_half = (uint32_t)(lane >> 4);         // 0/1 -> k byte-half
    const uint32_t b_row8 = (uint32_t)(lane & 7);          // row within 8x8
    const uint32_t b_khalf = (uint32_t)((lane >> 3) & 1);  // k 8-element half
    const uint32_t b_tsel = (uint32_t)(lane >> 4);         // which n-tile of the pair

    for (int ck = 0; ck < NCHUNK; ck++) {
        // chunk ck's load is complete once <=1 newer group is outstanding
        if (ck < NCHUNK - 1) cp_wait<1>(); else cp_wait<0>();
        __syncthreads();
        // Single barrier per chunk: stage (ck+2)%3 == (ck-1)%3 has no readers
        // past this barrier -> refill NOW so the load overlaps this chunk's MMAs.
        const int nk = ck + 2;
        if (nk < NCHUNK) {
            load_stage(sb + (uint32_t)(nk % NSTAGE) * STAGE_BYTES,
                       aBase + (size_t)nk * A_BLK,
                       bBase + (size_t)nk * B_BLK, tid);
            cp_commit();
        }

        const uint32_t sA = sb + (uint32_t)(ck % NSTAGE) * STAGE_BYTES;
        const uint32_t sB = sA + A_BLK;

#pragma unroll
        for (int ks = 0; ks < 4; ks++) {
            const uint32_t kb = (uint32_t)ks * 32u;        // 16 k-elems = 32 bytes
            // A fragments: 2 m-tiles of 16x16
            uint32_t a[2][4];
#pragma unroll
            for (int mt = 0; mt < 2; mt++) {
                uint32_t off = (uint32_t)(m_warp + mt * 16 + a_row) * 128u + kb + a_half * 16u;
                ldsm_x4(a[mt][0], a[mt][1], a[mt][2], a[mt][3], sA + swz(off));
            }
            // B fragments: n-major rows -> NON-trans ldmatrix; one x4 covers
            // n-tiles (2p,2p+1) x k-halves.
            uint32_t b[8][2];
#pragma unroll
            for (int p = 0; p < 4; p++) {
                uint32_t nrow = (uint32_t)n_warp + (uint32_t)p * 16u + b_tsel * 8u + b_row8;
                uint32_t off = nrow * 128u + kb + b_khalf * 16u;
                uint32_t r0, r1, r2, r3;
                ldsm_x4(r0, r1, r2, r3, sB + swz(off));
                b[p * 2 + 0][0] = r0; b[p * 2 + 0][1] = r1;
                b[p * 2 + 1][0] = r2; b[p * 2 + 1][1] = r3;
            }
#pragma unroll
            for (int mt = 0; mt < 2; mt++)
#pragma unroll
                for (int nt = 0; nt < 8; nt++)
                    mma16816(acc[mt][nt][0], acc[mt][nt][1], acc[mt][nt][2], acc[mt][nt][3],
                             a[mt][0], a[mt][1], a[mt][2], a[mt][3],
                             b[nt][0], b[nt][1]);
        }
        // no trailing barrier: next iteration's barrier provides the ordering
    }

    // ---------------- fused LSTM epilogue (smem-staged, coalesced) ----------------
    __syncthreads();   // all stage reads done before smem is repurposed
    float* gsm = reinterpret_cast<float*>(smem);
    {
        // Phase 1: acc -> smem gate matrix [128][EPI_STRIDE].
        // D frag: d0,d1 = row lane/4 cols 2q,2q+1; d2,d3 = row+8 (q = lane%4).
        const int q2 = (lane & 3) * 2;
        const int lr = lane >> 2;
#pragma unroll
        for (int mt = 0; mt < 2; mt++) {
            const int r0 = m_warp + mt * 16 + lr;
#pragma unroll
            for (int nt = 0; nt < 8; nt++) {
                const int cb = n_warp + nt * 8 + q2;
                *reinterpret_cast<float2*>(&gsm[r0 * EPI_STRIDE + cb]) =
                    make_float2(acc[mt][nt][0], acc[mt][nt][1]);
                *reinterpret_cast<float2*>(&gsm[(r0 + 8) * EPI_STRIDE + cb]) =
                    make_float2(acc[mt][nt][2], acc[mt][nt][3]);
            }
        }
    }
    __syncthreads();

    {
        // Phase 2: warp handles 16 rows; lane covers one j (32 j per CTA).
        // gates (i,f,g,o) adjacent in packed col dim -> one float4 per (row, j).
        const int j0 = tile_n * 32;                       // 32 hidden units per CTA
        const int jg = j0 + lane;
        const float4 bias = *reinterpret_cast<const float4*>(&g_bias[jg * 4]);
#pragma unroll
        for (int rr = 0; rr < 16; rr++) {
            const int rl = warp * 16 + rr;
            const int row = tile_m * TILE_M + rl;
            float4 gate = *reinterpret_cast<const float4*>(&gsm[rl * EPI_STRIDE + lane * 4]);
            float gi = fast_sigmoid(gate.x + bias.x);
            float gf = fast_sigmoid(gate.y + bias.y);
            float gg = fast_tanh(gate.z + bias.z);
            float go = fast_sigmoid(gate.w + bias.w);
            float cn = gf * cprev[(size_t)row * HID_N + jg] + gi * gg;
            float hn = go * fast_tanh(cn);
            out[(size_t)row * HID_N + jg] = hn;
            out[GATE_ELEMS + (size_t)row * HID_N + jg] = cn;
        }
    }
}

// ---------------------------------------------------------------- launch

extern "C" void kernel_launch(void* const* d_in, const int* in_sizes, int n_in,
                              void* d_out, int out_size)
{
    const float* input = (const float*)d_in[0];
    const float* h     = (const float*)d_in[1];
    const float* c     = (const float*)d_in[2];

    LstmPtrs P;
    P.wi[0] = (const float*)d_in[3];  P.bi[0] = (const float*)d_in[4];
    P.wh[0] = (const float*)d_in[5];  P.bh[0] = (const float*)d_in[6];
    P.wi[1] = (const float*)d_in[7];  P.bi[1] = (const float*)d_in[8];
    P.wh[1] = (const float*)d_in[9];  P.bh[1] = (const float*)d_in[10];
    P.wi[2] = (const float*)d_in[11]; P.bi[2] = (const float*)d_in[12];
    P.wh[2] = (const float*)d_in[13]; P.bh[2] = (const float*)d_in[14];
    P.wi[3] = (const float*)d_in[15]; P.bi[3] = (const float*)d_in[16];
    P.wh[3] = (const float*)d_in[17]; P.bh[3] = (const float*)d_in[18];

    float* out = (float*)d_out;

    // A units + B units = 2,097,152 -> 8192 blocks of 256
    pack_ab_kernel<<<8192, 256>>>(input, h, P);

    cudaFuncSetAttribute(lstm_mma_kernel,
                         cudaFuncAttributeMaxDynamicSharedMemorySize, SMEM_TOTAL);
    dim3 grid(NT_N, NT_M);     // (32, 32)
    lstm_mma_kernel<<<grid, 256, SMEM_TOTAL>>>(c, out);
}

// round 14
// speedup vs baseline: 1.0087x; 1.0087x over previous
#include <cuda_runtime.h>
#include <cuda_fp16.h>
#include <math.h>
#include <stdint.h>

// LSTM cell via warp-level fp16 mma.sync (base PTX ISA — safe for plain sm_103 target).
// R14: occupancy move. CTA tile 128x64 (8 warps, warp tile 32x32), 3 stages x 24KB
// -> 3 CTAs/SM (24 warps, was 16). Pure fp16 single pass, K = 2048 (rel_err 2.0e-4).
// Packed operands are pre-SW128-swizzled so stage loads are identity 16B copies.

#define BATCH_N 4096
#define HID_N   1024
#define GATE_ELEMS ((size_t)BATCH_N * HID_N)

#define NCHUNK  32          // K chunks of 64 fp16 (K = 2048)
#define ACHUNKS 32
#define BCHUNKS 32
#define TILE_M  128
#define TILE_N  64          // packed gate-rows r = 4*j + gate (16 j per CTA)
#define NT_M    32
#define NT_N    64
#define A_BLK   16384       // 128 rows * 128B
#define B_BLK   8192        // 64 rows * 128B
#define STAGE_BYTES (A_BLK + B_BLK)   // 24 KB
#define NSTAGE  3
#define SMEM_TOTAL (NSTAGE * STAGE_BYTES)   // 73728
#define EPI_STRIDE 68        // floats per row in epilogue smem (64 + 4 pad)

__device__ __align__(1024) unsigned char g_Apack[(size_t)NT_M * ACHUNKS * A_BLK];  // 16 MB
__device__ __align__(1024) unsigned char g_Bpack[(size_t)NT_N * BCHUNKS * B_BLK];  // 16 MB
__device__ float g_bias[4096];

// ---------------------------------------------------------------- PTX helpers (base ISA)
__device__ __forceinline__ uint32_t smem_u32(const void* p) {
    uint32_t a;
    asm("{ .reg .u64 t; cvta.to.shared.u64 t, %1; cvt.u32.u64 %0, t; }" : "=r"(a) : "l"(p));
    return a;
}
__device__ __forceinline__ void cp_async16(uint32_t dst, const void* src) {
    asm volatile("cp.async.cg.shared.global [%0], [%1], 16;" :: "r"(dst), "l"(src) : "memory");
}
__device__ __forceinline__ void cp_commit() {
    asm volatile("cp.async.commit_group;" ::: "memory");
}
template <int N>
__device__ __forceinline__ void cp_wait() {
    asm volatile("cp.async.wait_group %0;" :: "n"(N) : "memory");
}
__device__ __forceinline__ void ldsm_x4(uint32_t& r0, uint32_t& r1, uint32_t& r2, uint32_t& r3,
                                        uint32_t addr) {
    asm volatile("ldmatrix.sync.aligned.m8n8.x4.shared.b16 {%0,%1,%2,%3}, [%4];"
                 : "=r"(r0), "=r"(r1), "=r"(r2), "=r"(r3) : "r"(addr));
}
__device__ __forceinline__ void mma16816(float& d0, float& d1, float& d2, float& d3,
                                         uint32_t a0, uint32_t a1, uint32_t a2, uint32_t a3,
                                         uint32_t b0, uint32_t b1) {
    asm volatile("mma.sync.aligned.m16n8k16.row.col.f32.f16.f16.f32 "
                 "{%0,%1,%2,%3}, {%4,%5,%6,%7}, {%8,%9}, {%0,%1,%2,%3};"
                 : "+f"(d0), "+f"(d1), "+f"(d2), "+f"(d3)
                 : "r"(a0), "r"(a1), "r"(a2), "r"(a3), "r"(b0), "r"(b1));
}
__device__ __forceinline__ uint32_t swz(uint32_t off) { return off ^ ((off >> 3) & 0x70u); }

__device__ __forceinline__ float fast_sigmoid(float x) {
    return 1.0f / (1.0f + __expf(-x));
}
__device__ __forceinline__ float fast_tanh(float x) {
    return 2.0f / (1.0f + __expf(-2.0f * x)) - 1.0f;   // saturation-safe
}

// ---------------------------------------------------------------- pack kernels

struct LstmPtrs {
    const float* wi[4];
    const float* wh[4];
    const float* bi[4];
    const float* bh[4];
};

// A stored chunks 0..31 over k in [0,2048): [0:1024) input | [1024:2048) h. fp16.
__global__ __launch_bounds__(256)
void pack_a_kernel(const float* __restrict__ input, const float* __restrict__ hst)
{
    uint32_t u = blockIdx.x * 256u + threadIdx.x;     // one 16B unit (8 fp16)
    uint32_t tile_m = u / (ACHUNKS * 1024u);
    uint32_t rem = u % (ACHUNKS * 1024u);
    uint32_t ck = rem / 1024u;
    uint32_t w = rem % 1024u;
    uint32_t i = w >> 3;
    uint32_t kq = w & 7u;
    uint32_t row = tile_m * TILE_M + i;
    uint32_t k = ck * 64u + kq * 8u;        // [0, 2048)
    const float* src = (k < 1024u) ? input : hst;
    uint32_t col = k & 1023u;

    const float4* sp = reinterpret_cast<const float4*>(src + (size_t)row * HID_N + col);
    float4 v0 = sp[0], v1 = sp[1];
    float vals[8] = {v0.x, v0.y, v0.z, v0.w, v1.x, v1.y, v1.z, v1.w};
    __align__(16) __half ob[8];
#pragma unroll
    for (int t = 0; t < 8; t++) ob[t] = __float2half_rn(vals[t]);
    uint32_t off = i * 128u + kq * 16u;
    *reinterpret_cast<uint4*>(g_Apack + (size_t)(tile_m * ACHUNKS + ck) * A_BLK + swz(off)) =
        *reinterpret_cast<uint4*>(ob);
}

// B tiles of 64 packed rows r = 4*j + gate (0=i,1=f,2=g,3=o), n-major (row=n, 64 k cols).
// stored slots 0..31 over k in [0,2048): even 1024-seg = Wi, odd = Wh. fp16.
__global__ __launch_bounds__(256)
void pack_b_kernel(LstmPtrs P)
{
    uint32_t u = blockIdx.x * 256u + threadIdx.x;     // one 16B unit
    uint32_t tile_n = u / (BCHUNKS * 512u);
    uint32_t rem = u % (BCHUNKS * 512u);
    uint32_t cks = rem / 512u;              // storage slot 0..31
    uint32_t w = rem % 512u;
    uint32_t i = w >> 3;                    // row in tile (0..63)
    uint32_t kq = w & 7u;
    uint32_t r = tile_n * TILE_N + i;
    uint32_t j = r >> 2;
    uint32_t g = r & 3u;
    uint32_t k = cks * 64u + kq * 8u;       // [0, 2048)
    const float* src = (k >> 10) ? P.wh[g] : P.wi[g];
    uint32_t col = k & 1023u;

    const float4* sp = reinterpret_cast<const float4*>(src + (size_t)j * HID_N + col);
    float4 v0 = sp[0], v1 = sp[1];
    float vals[8] = {v0.x, v0.y, v0.z, v0.w, v1.x, v1.y, v1.z, v1.w};
    __align__(16) __half ob[8];
#pragma unroll
    for (int t = 0; t < 8; t++) ob[t] = __float2half_rn(vals[t]);
    uint32_t off = i * 128u + kq * 16u;
    *reinterpret_cast<uint4*>(g_Bpack + (size_t)(tile_n * BCHUNKS + cks) * B_BLK + swz(off)) =
        *reinterpret_cast<uint4*>(ob);

    // combined biases: one per packed row
    if (u < 4096u) {
        uint32_t rr = u, jj = rr >> 2, gg = rr & 3u;
        g_bias[rr] = P.bi[gg][jj] + P.bh[gg][jj];
    }
}

// ---------------------------------------------------------------- GEMM + fused LSTM epilogue

__device__ __forceinline__ void load_stage(uint32_t sdst, const unsigned char* aSrc,
                                           const unsigned char* bSrc, int tid)
{
#pragma unroll
    for (int i = 0; i < 4; i++)
        cp_async16(sdst + tid * 16 + i * 4096, aSrc + tid * 16 + i * 4096);
#pragma unroll
    for (int i = 0; i < 2; i++)
        cp_async16(sdst + A_BLK + tid * 16 + i * 4096, bSrc + tid * 16 + i * 4096);
}

__global__ __launch_bounds__(256, 3)
void lstm_mma_kernel(const float* __restrict__ cprev, float* __restrict__ out)
{
    extern __shared__ __align__(1024) unsigned char smem[];
    const uint32_t sb = smem_u32(smem);
    const int tid = threadIdx.x;
    const int warp = tid >> 5, lane = tid & 31;
    const int wm = warp & 3, wn = warp >> 2;      // 4 (M) x 2 (N) warps, warp tile 32x32
    const int m_warp = wm * 32, n_warp = wn * 32;
    const int tile_n = blockIdx.x, tile_m = blockIdx.y;

    const unsigned char* aBase = g_Apack + (size_t)tile_m * ACHUNKS * A_BLK;
    const unsigned char* bBase = g_Bpack + (size_t)tile_n * BCHUNKS * B_BLK;

    float acc[2][4][4];
#pragma unroll
    for (int mt = 0; mt < 2; mt++)
#pragma unroll
        for (int nt = 0; nt < 4; nt++)
#pragma unroll
            for (int e = 0; e < 4; e++) acc[mt][nt][e] = 0.0f;

    // prefetch stages 0,1
    load_stage(sb, aBase, bBase, tid);
    cp_commit();
    load_stage(sb + STAGE_BYTES, aBase + A_BLK, bBase + B_BLK, tid);
    cp_commit();

    // ldmatrix lane addressing
    const uint32_t a_row = (uint32_t)(lane & 15);          // 0..15
    const uint32_t a_half = (uint32_t)(lane >> 4);         // 0/1 -> k byte-half
    const uint32_t b_row8 = (uint32_t)(lane & 7);          // row within 8x8
    const uint32_t b_khalf = (uint32_t)((lane >> 3) & 1);  // k 8-element half
    const uint32_t b_tsel = (uint32_t)(lane >> 4);         // which n-tile of the pair

    for (int ck = 0; ck < NCHUNK; ck++) {
        // chunk ck's load is complete once <=1 newer group is outstanding
        if (ck < NCHUNK - 1) cp_wait<1>(); else cp_wait<0>();
        __syncthreads();
        // Single barrier per chunk: stage (ck+2)%3 == (ck-1)%3 has no readers
        // past this barrier -> refill NOW so the load overlaps this chunk's MMAs.
        const int nk = ck + 2;
        if (nk < NCHUNK) {
            load_stage(sb + (uint32_t)(nk % NSTAGE) * STAGE_BYTES,
                       aBase + (size_t)nk * A_BLK,
                       bBase + (size_t)nk * B_BLK, tid);
            cp_commit();
        }

        const uint32_t sA = sb + (uint32_t)(ck % NSTAGE) * STAGE_BYTES;
        const uint32_t sB = sA + A_BLK;

#pragma unroll
        for (int ks = 0; ks < 4; ks++) {
            const uint32_t kb = (uint32_t)ks * 32u;        // 16 k-elems = 32 bytes
            // A fragments: 2 m-tiles of 16x16
            uint32_t a[2][4];
#pragma unroll
            for (int mt = 0; mt < 2; mt++) {
                uint32_t off = (uint32_t)(m_warp + mt * 16 + a_row) * 128u + kb + a_half * 16u;
                ldsm_x4(a[mt][0], a[mt][1], a[mt][2], a[mt][3], sA + swz(off));
            }
            // B fragments: n-major rows -> NON-trans ldmatrix; one x4 covers
            // n-tiles (2p,2p+1) x k-halves. 4 n-tiles of 8 -> 2 x4 loads.
            uint32_t b[4][2];
#pragma unroll
            for (int p = 0; p < 2; p++) {
                uint32_t nrow = (uint32_t)n_warp + (uint32_t)p * 16u + b_tsel * 8u + b_row8;
                uint32_t off = nrow * 128u + kb + b_khalf * 16u;
                uint32_t r0, r1, r2, r3;
                ldsm_x4(r0, r1, r2, r3, sB + swz(off));
                b[p * 2 + 0][0] = r0; b[p * 2 + 0][1] = r1;
                b[p * 2 + 1][0] = r2; b[p * 2 + 1][1] = r3;
            }
#pragma unroll
            for (int mt = 0; mt < 2; mt++)
#pragma unroll
                for (int nt = 0; nt < 4; nt++)
                    mma16816(acc[mt][nt][0], acc[mt][nt][1], acc[mt][nt][2], acc[mt][nt][3],
                             a[mt][0], a[mt][1], a[mt][2], a[mt][3],
                             b[nt][0], b[nt][1]);
        }
        // no trailing barrier: next iteration's barrier provides the ordering
    }

    // ---------------- fused LSTM epilogue (smem-staged, coalesced) ----------------
    __syncthreads();   // all stage reads done before smem is repurposed
    float* gsm = reinterpret_cast<float*>(smem);
    {
        // Phase 1: acc -> smem gate matrix [128][EPI_STRIDE].
        // D frag: d0,d1 = row lane/4 cols 2q,2q+1; d2,d3 = row+8 (q = lane%4).
        const int q2 = (lane & 3) * 2;
        const int lr = lane >> 2;
#pragma unroll
        for (int mt = 0; mt < 2; mt++) {
            const int r0 = m_warp + mt * 16 + lr;
#pragma unroll
            for (int nt = 0; nt < 4; nt++) {
                const int cb = n_warp + nt * 8 + q2;
                *reinterpret_cast<float2*>(&gsm[r0 * EPI_STRIDE + cb]) =
                    make_float2(acc[mt][nt][0], acc[mt][nt][1]);
                *reinterpret_cast<float2*>(&gsm[(r0 + 8) * EPI_STRIDE + cb]) =
                    make_float2(acc[mt][nt][2], acc[mt][nt][3]);
            }
        }
    }
    __syncthreads();

    {
        // Phase 2: 128 rows x 16 j per CTA. Thread t: j = t&15, rows (t>>4)*8..+8.
        // gates (i,f,g,o) adjacent in packed col dim -> one float4 per (row, j).
        const int jl = tid & 15;
        const int rseg = tid >> 4;                        // 0..15 -> 8 rows each
        const int jg = tile_n * 16 + jl;
        const float4 bias = *reinterpret_cast<const float4*>(&g_bias[jg * 4]);
#pragma unroll
        for (int rr = 0; rr < 8; rr++) {
            const int rl = rseg * 8 + rr;
            const int row = tile_m * TILE_M + rl;
            float4 gate = *reinterpret_cast<const float4*>(&gsm[rl * EPI_STRIDE + jl * 4]);
            float gi = fast_sigmoid(gate.x + bias.x);
            float gf = fast_sigmoid(gate.y + bias.y);
            float gg = fast_tanh(gate.z + bias.z);
            float go = fast_sigmoid(gate.w + bias.w);
            float cn = gf * cprev[(size_t)row * HID_N + jg] + gi * gg;
            float hn = go * fast_tanh(cn);
            out[(size_t)row * HID_N + jg] = hn;
            out[GATE_ELEMS + (size_t)row * HID_N + jg] = cn;
        }
    }
}

// ---------------------------------------------------------------- launch

extern "C" void kernel_launch(void* const* d_in, const int* in_sizes, int n_in,
                              void* d_out, int out_size)
{
    const float* input = (const float*)d_in[0];
    const float* h     = (const float*)d_in[1];
    const float* c     = (const float*)d_in[2];

    LstmPtrs P;
    P.wi[0] = (const float*)d_in[3];  P.bi[0] = (const float*)d_in[4];
    P.wh[0] = (const float*)d_in[5];  P.bh[0] = (const float*)d_in[6];
    P.wi[1] = (const float*)d_in[7];  P.bi[1] = (const float*)d_in[8];
    P.wh[1] = (const float*)d_in[9];  P.bh[1] = (const float*)d_in[10];
    P.wi[2] = (const float*)d_in[11]; P.bi[2] = (const float*)d_in[12];
    P.wh[2] = (const float*)d_in[13]; P.bh[2] = (const float*)d_in[14];
    P.wi[3] = (const float*)d_in[15]; P.bi[3] = (const float*)d_in[16];
    P.wh[3] = (const float*)d_in[17]; P.bh[3] = (const float*)d_in[18];

    float* out = (float*)d_out;

    // A: 32*32*1024 = 1,048,576 units -> 4096 blocks
    pack_a_kernel<<<4096, 256>>>(input, h);
    // B: 64*32*512 = 1,048,576 units -> 4096 blocks
    pack_b_kernel<<<4096, 256>>>(P);

    cudaFuncSetAttribute(lstm_mma_kernel,
                         cudaFuncAttributeMaxDynamicSharedMemorySize, SMEM_TOTAL);
    dim3 grid(NT_N, NT_M);     // (64, 32)
    lstm_mma_kernel<<<grid, 256, SMEM_TOTAL>>>(c, out);
}

// round 16
// speedup vs baseline: 1.1134x; 1.1039x over previous
#include <cuda_runtime.h>
#include <cuda_fp16.h>
#include <math.h>
#include <stdint.h>

// LSTM cell via warp-level fp16 mma.sync (base PTX ISA — safe for plain sm_103 target).
// R16: R12 pipeline restored exactly (wait -> sync -> refill -> MMA; the R15 reorder
// violated cp.async cross-thread visibility and produced NaN). Epilogue adds a
// register cprev prefetch AFTER phase-1 staging (acc regs dead) and BEFORE the
// phase-2 barrier, hiding the LDG latency behind the join.
// Pure fp16 single pass, K = 2048 (measured rel_err 2.0e-4, threshold 1e-3).

#define BATCH_N 4096
#define HID_N   1024
#define GATE_ELEMS ((size_t)BATCH_N * HID_N)

#define NCHUNK  32          // K chunks of 64 fp16 (K = 2048)
#define ACHUNKS 32
#define BCHUNKS 32
#define TILE_M  128
#define TILE_N  128         // packed gate-rows r = 4*j + gate
#define NT_M    32
#define NT_N    32
#define A_BLK   16384       // 128 rows * 128B
#define B_BLK   16384
#define STAGE_BYTES (A_BLK + B_BLK)   // 32 KB
#define NSTAGE  3
#define SMEM_TOTAL (NSTAGE * STAGE_BYTES)   // 98304
#define EPI_STRIDE 132       // floats per row in epilogue smem (128 + 4 pad)

__device__ __align__(1024) unsigned char g_Apack[(size_t)NT_M * ACHUNKS * A_BLK];  // 16 MB
__device__ __align__(1024) unsigned char g_Bpack[(size_t)NT_N * BCHUNKS * B_BLK];  // 16 MB
__device__ float g_bias[4096];

// ---------------------------------------------------------------- PTX helpers (base ISA)
__device__ __forceinline__ uint32_t smem_u32(const void* p) {
    uint32_t a;
    asm("{ .reg .u64 t; cvta.to.shared.u64 t, %1; cvt.u32.u64 %0, t; }" : "=r"(a) : "l"(p));
    return a;
}
__device__ __forceinline__ void cp_async16(uint32_t dst, const void* src) {
    asm volatile("cp.async.cg.shared.global [%0], [%1], 16;" :: "r"(dst), "l"(src) : "memory");
}
__device__ __forceinline__ void cp_commit() {
    asm volatile("cp.async.commit_group;" ::: "memory");
}
template <int N>
__device__ __forceinline__ void cp_wait() {
    asm volatile("cp.async.wait_group %0;" :: "n"(N) : "memory");
}
__device__ __forceinline__ void ldsm_x4(uint32_t& r0, uint32_t& r1, uint32_t& r2, uint32_t& r3,
                                        uint32_t addr) {
    asm volatile("ldmatrix.sync.aligned.m8n8.x4.shared.b16 {%0,%1,%2,%3}, [%4];"
                 : "=r"(r0), "=r"(r1), "=r"(r2), "=r"(r3) : "r"(addr));
}
__device__ __forceinline__ void mma16816(float& d0, float& d1, float& d2, float& d3,
                                         uint32_t a0, uint32_t a1, uint32_t a2, uint32_t a3,
                                         uint32_t b0, uint32_t b1) {
    asm volatile("mma.sync.aligned.m16n8k16.row.col.f32.f16.f16.f32 "
                 "{%0,%1,%2,%3}, {%4,%5,%6,%7}, {%8,%9}, {%0,%1,%2,%3};"
                 : "+f"(d0), "+f"(d1), "+f"(d2), "+f"(d3)
                 : "r"(a0), "r"(a1), "r"(a2), "r"(a3), "r"(b0), "r"(b1));
}
__device__ __forceinline__ uint32_t swz(uint32_t off) { return off ^ ((off >> 3) & 0x70u); }

__device__ __forceinline__ float fast_sigmoid(float x) {
    return 1.0f / (1.0f + __expf(-x));
}
__device__ __forceinline__ float fast_tanh(float x) {
    return 2.0f / (1.0f + __expf(-2.0f * x)) - 1.0f;   // saturation-safe
}

// ---------------------------------------------------------------- pack kernels

struct LstmPtrs {
    const float* wi[4];
    const float* wh[4];
    const float* bi[4];
    const float* bh[4];
};

// A stored chunks 0..31 over k in [0,2048): [0:1024) input | [1024:2048) h. fp16.
__global__ __launch_bounds__(256)
void pack_a_kernel(const float* __restrict__ input, const float* __restrict__ hst)
{
    uint32_t u = blockIdx.x * 256u + threadIdx.x;     // one 16B unit (8 fp16)
    uint32_t tile_m = u / (ACHUNKS * 1024u);
    uint32_t rem = u % (ACHUNKS * 1024u);
    uint32_t ck = rem / 1024u;
    uint32_t w = rem % 1024u;
    uint32_t i = w >> 3;
    uint32_t kq = w & 7u;
    uint32_t row = tile_m * TILE_M + i;
    uint32_t k = ck * 64u + kq * 8u;        // [0, 2048)
    const float* src = (k < 1024u) ? input : hst;
    uint32_t col = k & 1023u;

    const float4* sp = reinterpret_cast<const float4*>(src + (size_t)row * HID_N + col);
    float4 v0 = sp[0], v1 = sp[1];
    float vals[8] = {v0.x, v0.y, v0.z, v0.w, v1.x, v1.y, v1.z, v1.w};
    __align__(16) __half ob[8];
#pragma unroll
    for (int t = 0; t < 8; t++) ob[t] = __float2half_rn(vals[t]);
    uint32_t off = i * 128u + kq * 16u;
    *reinterpret_cast<uint4*>(g_Apack + (size_t)(tile_m * ACHUNKS + ck) * A_BLK + swz(off)) =
        *reinterpret_cast<uint4*>(ob);
}

// B tiles of 128 packed rows r = 4*j + gate (0=i,1=f,2=g,3=o), n-major (row=n, 64 k cols).
// stored slots 0..31 over k in [0,2048): even 1024-seg = Wi, odd = Wh. fp16.
__global__ __launch_bounds__(256)
void pack_b_kernel(LstmPtrs P)
{
    uint32_t u = blockIdx.x * 256u + threadIdx.x;
    uint32_t tile_n = u / (BCHUNKS * 1024u);
    uint32_t rem = u % (BCHUNKS * 1024u);
    uint32_t cks = rem / 1024u;             // storage slot 0..31
    uint32_t w = rem % 1024u;
    uint32_t i = w >> 3;                    // row in tile (0..127)
    uint32_t kq = w & 7u;
    uint32_t r = tile_n * TILE_N + i;
    uint32_t j = r >> 2;
    uint32_t g = r & 3u;
    uint32_t k = cks * 64u + kq * 8u;       // [0, 2048)
    const float* src = (k >> 10) ? P.wh[g] : P.wi[g];
    uint32_t col = k & 1023u;

    const float4* sp = reinterpret_cast<const float4*>(src + (size_t)j * HID_N + col);
    float4 v0 = sp[0], v1 = sp[1];
    float vals[8] = {v0.x, v0.y, v0.z, v0.w, v1.x, v1.y, v1.z, v1.w};
    __align__(16) __half ob[8];
#pragma unroll
    for (int t = 0; t < 8; t++) ob[t] = __float2half_rn(vals[t]);
    uint32_t off = i * 128u + kq * 16u;
    *reinterpret_cast<uint4*>(g_Bpack + (size_t)(tile_n * BCHUNKS + cks) * B_BLK + swz(off)) =
        *reinterpret_cast<uint4*>(ob);

    // combined biases: one per packed row
    if (u < 4096u) {
        uint32_t rr = u, jj = rr >> 2, gg = rr & 3u;
        g_bias[rr] = P.bi[gg][jj] + P.bh[gg][jj];
    }
}

// ---------------------------------------------------------------- GEMM + fused LSTM epilogue

__device__ __forceinline__ void load_stage(uint32_t sdst, const unsigned char* aSrc,
                                           const unsigned char* bSrc, int tid)
{
#pragma unroll
    for (int i = 0; i < 4; i++)
        cp_async16(sdst + tid * 16 + i * 4096, aSrc + tid * 16 + i * 4096);
#pragma unroll
    for (int i = 0; i < 4; i++)
        cp_async16(sdst + A_BLK + tid * 16 + i * 4096, bSrc + tid * 16 + i * 4096);
}

__global__ __launch_bounds__(256, 2)
void lstm_mma_kernel(const float* __restrict__ cprev, float* __restrict__ out)
{
    extern __shared__ __align__(1024) unsigned char smem[];
    const uint32_t sb = smem_u32(smem);
    const int tid = threadIdx.x;
    const int warp = tid >> 5, lane = tid & 31;
    const int wm = warp & 3, wn = warp >> 2;      // 4 (M) x 2 (N) warps, warp tile 32x64
    const int m_warp = wm * 32, n_warp = wn * 64;
    const int tile_n = blockIdx.x, tile_m = blockIdx.y;

    const unsigned char* aBase = g_Apack + (size_t)tile_m * ACHUNKS * A_BLK;
    const unsigned char* bBase = g_Bpack + (size_t)tile_n * BCHUNKS * B_BLK;

    float acc[2][8][4];
#pragma unroll
    for (int mt = 0; mt < 2; mt++)
#pragma unroll
        for (int nt = 0; nt < 8; nt++)
#pragma unroll
            for (int e = 0; e < 4; e++) acc[mt][nt][e] = 0.0f;

    // prefetch stages 0,1
    load_stage(sb, aBase, bBase, tid);
    cp_commit();
    load_stage(sb + STAGE_BYTES, aBase + A_BLK, bBase + B_BLK, tid);
    cp_commit();

    // ldmatrix lane addressing
    const uint32_t a_row = (uint32_t)(lane & 15);          // 0..15
    const uint32_t a_half = (uint32_t)(lane >> 4);         // 0/1 -> k byte-half
    const uint32_t b_row8 = (uint32_t)(lane & 7);          // row within 8x8
    const uint32_t b_khalf = (uint32_t)((lane >> 3) & 1);  // k 8-element half
    const uint32_t b_tsel = (uint32_t)(lane >> 4);         // which n-tile of the pair

    for (int ck = 0; ck < NCHUNK; ck++) {
        // chunk ck's load is complete once <=1 newer group is outstanding.
        // wait BEFORE the barrier: every thread's copies for stage ck are done,
        // then the barrier publishes them CTA-wide (cp.async visibility contract).
        if (ck < NCHUNK - 1) cp_wait<1>(); else cp_wait<0>();
        __syncthreads();
        // Stage (ck+2)%3 == (ck-1)%3 has no readers past this barrier -> refill
        // now so the load overlaps this chunk's MMAs.
        const int nk = ck + 2;
        if (nk < NCHUNK) {
            load_stage(sb + (uint32_t)(nk % NSTAGE) * STAGE_BYTES,
                       aBase + (size_t)nk * A_BLK,
                       bBase + (size_t)nk * B_BLK, tid);
            cp_commit();
        }

        const uint32_t sA = sb + (uint32_t)(ck % NSTAGE) * STAGE_BYTES;
        const uint32_t sB = sA + A_BLK;

#pragma unroll
        for (int ks = 0; ks < 4; ks++) {
            const uint32_t kb = (uint32_t)ks * 32u;        // 16 k-elems = 32 bytes
            // A fragments: 2 m-tiles of 16x16
            uint32_t a[2][4];
#pragma unroll
            for (int mt = 0; mt < 2; mt++) {
                uint32_t off = (uint32_t)(m_warp + mt * 16 + a_row) * 128u + kb + a_half * 16u;
                ldsm_x4(a[mt][0], a[mt][1], a[mt][2], a[mt][3], sA + swz(off));
            }
            // B fragments: n-major rows -> NON-trans ldmatrix; one x4 covers
            // n-tiles (2p,2p+1) x k-halves.
            uint32_t b[8][2];
#pragma unroll
            for (int p = 0; p < 4; p++) {
                uint32_t nrow = (uint32_t)n_warp + (uint32_t)p * 16u + b_tsel * 8u + b_row8;
                uint32_t off = nrow * 128u + kb + b_khalf * 16u;
                uint32_t r0, r1, r2, r3;
                ldsm_x4(r0, r1, r2, r3, sB + swz(off));
                b[p * 2 + 0][0] = r0; b[p * 2 + 0][1] = r1;
                b[p * 2 + 1][0] = r2; b[p * 2 + 1][1] = r3;
            }
#pragma unroll
            for (int mt = 0; mt < 2; mt++)
#pragma unroll
                for (int nt = 0; nt < 8; nt++)
                    mma16816(acc[mt][nt][0], acc[mt][nt][1], acc[mt][nt][2], acc[mt][nt][3],
                             a[mt][0], a[mt][1], a[mt][2], a[mt][3],
                             b[nt][0], b[nt][1]);
        }
        // no trailing barrier: next iteration's barrier provides the ordering
    }

    // ---------------- fused LSTM epilogue (smem-staged, coalesced) ----------------
    __syncthreads();   // all stage reads done before smem is repurposed
    float* gsm = reinterpret_cast<float*>(smem);
    {
        // Phase 1: acc -> smem gate matrix [128][EPI_STRIDE].
        // D frag: d0,d1 = row lane/4 cols 2q,2q+1; d2,d3 = row+8 (q = lane%4).
        const int q2 = (lane & 3) * 2;
        const int lr = lane >> 2;
#pragma unroll
        for (int mt = 0; mt < 2; mt++) {
            const int r0 = m_warp + mt * 16 + lr;
#pragma unroll
            for (int nt = 0; nt < 8; nt++) {
                const int cb = n_warp + nt * 8 + q2;
                *reinterpret_cast<float2*>(&gsm[r0 * EPI_STRIDE + cb]) =
                    make_float2(acc[mt][nt][0], acc[mt][nt][1]);
                *reinterpret_cast<float2*>(&gsm[(r0 + 8) * EPI_STRIDE + cb]) =
                    make_float2(acc[mt][nt][2], acc[mt][nt][3]);
            }
        }
    }

    // cprev prefetch: acc registers are dead after phase-1 staging, so cpv[16]
    // fits without spilling; the 16 independent LDGs fly during the barrier join.
    const int jg = tile_n * 32 + lane;
    float cpv[16];
#pragma unroll
    for (int rr = 0; rr < 16; rr++) {
        const int row = tile_m * TILE_M + warp * 16 + rr;
        cpv[rr] = cprev[(size_t)row * HID_N + jg];
    }

    __syncthreads();

    {
        // Phase 2: warp handles 16 rows; lane covers one j (32 j per CTA).
        // gates (i,f,g,o) adjacent in packed col dim -> one float4 per (row, j).
        const float4 bias = *reinterpret_cast<const float4*>(&g_bias[jg * 4]);
#pragma unroll
        for (int rr = 0; rr < 16; rr++) {
            const int rl = warp * 16 + rr;
            const int row = tile_m * TILE_M + rl;
            float4 gate = *reinterpret_cast<const float4*>(&gsm[rl * EPI_STRIDE + lane * 4]);
            float gi = fast_sigmoid(gate.x + bias.x);
            float gf = fast_sigmoid(gate.y + bias.y);
            float gg = fast_tanh(gate.z + bias.z);
            float go = fast_sigmoid(gate.w + bias.w);
            float cn = gf * cpv[rr] + gi * gg;
            float hn = go * fast_tanh(cn);
            out[(size_t)row * HID_N + jg] = hn;
            out[GATE_ELEMS + (size_t)row * HID_N + jg] = cn;
        }
    }
}

// ---------------------------------------------------------------- launch

extern "C" void kernel_launch(void* const* d_in, const int* in_sizes, int n_in,
                              void* d_out, int out_size)
{
    const float* input = (const float*)d_in[0];
    const float* h     = (const float*)d_in[1];
    const float* c     = (const float*)d_in[2];

    LstmPtrs P;
    P.wi[0] = (const float*)d_in[3];  P.bi[0] = (const float*)d_in[4];
    P.wh[0] = (const float*)d_in[5];  P.bh[0] = (const float*)d_in[6];
    P.wi[1] = (const float*)d_in[7];  P.bi[1] = (const float*)d_in[8];
    P.wh[1] = (const float*)d_in[9];  P.bh[1] = (const float*)d_in[10];
    P.wi[2] = (const float*)d_in[11]; P.bi[2] = (const float*)d_in[12];
    P.wh[2] = (const float*)d_in[13]; P.bh[2] = (const float*)d_in[14];
    P.wi[3] = (const float*)d_in[15]; P.bi[3] = (const float*)d_in[16];
    P.wh[3] = (const float*)d_in[17]; P.bh[3] = (const float*)d_in[18];

    float* out = (float*)d_out;

    // A: 32*32*1024 = 1,048,576 units -> 4096 blocks
    pack_a_kernel<<<4096, 256>>>(input, h);
    // B: 32*32*1024 = 1,048,576 units -> 4096 blocks
    pack_b_kernel<<<4096, 256>>>(P);

    cudaFuncSetAttribute(lstm_mma_kernel,
                         cudaFuncAttributeMaxDynamicSharedMemorySize, SMEM_TOTAL);
    dim3 grid(NT_N, NT_M);     // (32, 32)
    lstm_mma_kernel<<<grid, 256, SMEM_TOTAL>>>(c, out);
}

// round 17
// speedup vs baseline: 1.1491x; 1.0321x over previous
#include <cuda_runtime.h>
#include <cuda_fp16.h>
#include <math.h>
#include <stdint.h>

// LSTM cell via warp-level fp16 mma.sync (base PTX ISA — safe for plain sm_103 target).
// R17: R16 base (banked 200.9us) + pack kernels at 2 units/thread (higher MLP) +
// chunk loop unrolled x3 (stage addresses become immediates).
// Pure fp16 single pass, K = 2048 (measured rel_err 2.0e-4, threshold 1e-3).

#define BATCH_N 4096
#define HID_N   1024
#define GATE_ELEMS ((size_t)BATCH_N * HID_N)

#define NCHUNK  32          // K chunks of 64 fp16 (K = 2048)
#define ACHUNKS 32
#define BCHUNKS 32
#define TILE_M  128
#define TILE_N  128         // packed gate-rows r = 4*j + gate
#define NT_M    32
#define NT_N    32
#define A_BLK   16384       // 128 rows * 128B
#define B_BLK   16384
#define STAGE_BYTES (A_BLK + B_BLK)   // 32 KB
#define NSTAGE  3
#define SMEM_TOTAL (NSTAGE * STAGE_BYTES)   // 98304
#define EPI_STRIDE 132       // floats per row in epilogue smem (128 + 4 pad)

__device__ __align__(1024) unsigned char g_Apack[(size_t)NT_M * ACHUNKS * A_BLK];  // 16 MB
__device__ __align__(1024) unsigned char g_Bpack[(size_t)NT_N * BCHUNKS * B_BLK];  // 16 MB
__device__ float g_bias[4096];

// ---------------------------------------------------------------- PTX helpers (base ISA)
__device__ __forceinline__ uint32_t smem_u32(const void* p) {
    uint32_t a;
    asm("{ .reg .u64 t; cvta.to.shared.u64 t, %1; cvt.u32.u64 %0, t; }" : "=r"(a) : "l"(p));
    return a;
}
__device__ __forceinline__ void cp_async16(uint32_t dst, const void* src) {
    asm volatile("cp.async.cg.shared.global [%0], [%1], 16;" :: "r"(dst), "l"(src) : "memory");
}
__device__ __forceinline__ void cp_commit() {
    asm volatile("cp.async.commit_group;" ::: "memory");
}
template <int N>
__device__ __forceinline__ void cp_wait() {
    asm volatile("cp.async.wait_group %0;" :: "n"(N) : "memory");
}
__device__ __forceinline__ void ldsm_x4(uint32_t& r0, uint32_t& r1, uint32_t& r2, uint32_t& r3,
                                        uint32_t addr) {
    asm volatile("ldmatrix.sync.aligned.m8n8.x4.shared.b16 {%0,%1,%2,%3}, [%4];"
                 : "=r"(r0), "=r"(r1), "=r"(r2), "=r"(r3) : "r"(addr));
}
__device__ __forceinline__ void mma16816(float& d0, float& d1, float& d2, float& d3,
                                         uint32_t a0, uint32_t a1, uint32_t a2, uint32_t a3,
                                         uint32_t b0, uint32_t b1) {
    asm volatile("mma.sync.aligned.m16n8k16.row.col.f32.f16.f16.f32 "
                 "{%0,%1,%2,%3}, {%4,%5,%6,%7}, {%8,%9}, {%0,%1,%2,%3};"
                 : "+f"(d0), "+f"(d1), "+f"(d2), "+f"(d3)
                 : "r"(a0), "r"(a1), "r"(a2), "r"(a3), "r"(b0), "r"(b1));
}
__device__ __forceinline__ uint32_t swz(uint32_t off) { return off ^ ((off >> 3) & 0x70u); }

__device__ __forceinline__ float fast_sigmoid(float x) {
    return 1.0f / (1.0f + __expf(-x));
}
__device__ __forceinline__ float fast_tanh(float x) {
    return 2.0f / (1.0f + __expf(-2.0f * x)) - 1.0f;   // saturation-safe
}

// ---------------------------------------------------------------- pack kernels

struct LstmPtrs {
    const float* wi[4];
    const float* wh[4];
    const float* bi[4];
    const float* bh[4];
};

// A stored chunks 0..31 over k in [0,2048): [0:1024) input | [1024:2048) h. fp16.
// 2 consecutive 16B units per thread (64B contiguous source read -> MLP 4).
__global__ __launch_bounds__(256)
void pack_a_kernel(const float* __restrict__ input, const float* __restrict__ hst)
{
    uint32_t ubase = (blockIdx.x * 256u + threadIdx.x) * 2u;
#pragma unroll
    for (int rep = 0; rep < 2; rep++) {
        uint32_t u = ubase + (uint32_t)rep;
        uint32_t tile_m = u / (ACHUNKS * 1024u);
        uint32_t rem = u % (ACHUNKS * 1024u);
        uint32_t ck = rem / 1024u;
        uint32_t w = rem % 1024u;
        uint32_t i = w >> 3;
        uint32_t kq = w & 7u;
        uint32_t row = tile_m * TILE_M + i;
        uint32_t k = ck * 64u + kq * 8u;        // [0, 2048)
        const float* src = (k < 1024u) ? input : hst;
        uint32_t col = k & 1023u;

        const float4* sp = reinterpret_cast<const float4*>(src + (size_t)row * HID_N + col);
        float4 v0 = sp[0], v1 = sp[1];
        float vals[8] = {v0.x, v0.y, v0.z, v0.w, v1.x, v1.y, v1.z, v1.w};
        __align__(16) __half ob[8];
#pragma unroll
        for (int t = 0; t < 8; t++) ob[t] = __float2half_rn(vals[t]);
        uint32_t off = i * 128u + kq * 16u;
        *reinterpret_cast<uint4*>(g_Apack + (size_t)(tile_m * ACHUNKS + ck) * A_BLK + swz(off)) =
            *reinterpret_cast<uint4*>(ob);
    }
}

// B tiles of 128 packed rows r = 4*j + gate (0=i,1=f,2=g,3=o), n-major (row=n, 64 k cols).
// stored slots 0..31 over k in [0,2048): even 1024-seg = Wi, odd = Wh. fp16.
// 2 consecutive 16B units per thread.
__global__ __launch_bounds__(256)
void pack_b_kernel(LstmPtrs P)
{
    uint32_t ubase = (blockIdx.x * 256u + threadIdx.x) * 2u;
#pragma unroll
    for (int rep = 0; rep < 2; rep++) {
        uint32_t u = ubase + (uint32_t)rep;
        uint32_t tile_n = u / (BCHUNKS * 1024u);
        uint32_t rem = u % (BCHUNKS * 1024u);
        uint32_t cks = rem / 1024u;             // storage slot 0..31
        uint32_t w = rem % 1024u;
        uint32_t i = w >> 3;                    // row in tile (0..127)
        uint32_t kq = w & 7u;
        uint32_t r = tile_n * TILE_N + i;
        uint32_t j = r >> 2;
        uint32_t g = r & 3u;
        uint32_t k = cks * 64u + kq * 8u;       // [0, 2048)
        const float* src = (k >> 10) ? P.wh[g] : P.wi[g];
        uint32_t col = k & 1023u;

        const float4* sp = reinterpret_cast<const float4*>(src + (size_t)j * HID_N + col);
        float4 v0 = sp[0], v1 = sp[1];
        float vals[8] = {v0.x, v0.y, v0.z, v0.w, v1.x, v1.y, v1.z, v1.w};
        __align__(16) __half ob[8];
#pragma unroll
        for (int t = 0; t < 8; t++) ob[t] = __float2half_rn(vals[t]);
        uint32_t off = i * 128u + kq * 16u;
        *reinterpret_cast<uint4*>(g_Bpack + (size_t)(tile_n * BCHUNKS + cks) * B_BLK + swz(off)) =
            *reinterpret_cast<uint4*>(ob);

        // combined biases: one per packed row
        if (u < 4096u) {
            uint32_t rr = u, jj = rr >> 2, gg = rr & 3u;
            g_bias[rr] = P.bi[gg][jj] + P.bh[gg][jj];
        }
    }
}

// ---------------------------------------------------------------- GEMM + fused LSTM epilogue

__device__ __forceinline__ void load_stage(uint32_t sdst, const unsigned char* aSrc,
                                           const unsigned char* bSrc, int tid)
{
#pragma unroll
    for (int i = 0; i < 4; i++)
        cp_async16(sdst + tid * 16 + i * 4096, aSrc + tid * 16 + i * 4096);
#pragma unroll
    for (int i = 0; i < 4; i++)
        cp_async16(sdst + A_BLK + tid * 16 + i * 4096, bSrc + tid * 16 + i * 4096);
}

__global__ __launch_bounds__(256, 2)
void lstm_mma_kernel(const float* __restrict__ cprev, float* __restrict__ out)
{
    extern __shared__ __align__(1024) unsigned char smem[];
    const uint32_t sb = smem_u32(smem);
    const int tid = threadIdx.x;
    const int warp = tid >> 5, lane = tid & 31;
    const int wm = warp & 3, wn = warp >> 2;      // 4 (M) x 2 (N) warps, warp tile 32x64
    const int m_warp = wm * 32, n_warp = wn * 64;
    const int tile_n = blockIdx.x, tile_m = blockIdx.y;

    const unsigned char* aBase = g_Apack + (size_t)tile_m * ACHUNKS * A_BLK;
    const unsigned char* bBase = g_Bpack + (size_t)tile_n * BCHUNKS * B_BLK;

    float acc[2][8][4];
#pragma unroll
    for (int mt = 0; mt < 2; mt++)
#pragma unroll
        for (int nt = 0; nt < 8; nt++)
#pragma unroll
            for (int e = 0; e < 4; e++) acc[mt][nt][e] = 0.0f;

    // prefetch stages 0,1
    load_stage(sb, aBase, bBase, tid);
    cp_commit();
    load_stage(sb + STAGE_BYTES, aBase + A_BLK, bBase + B_BLK, tid);
    cp_commit();

    // ldmatrix lane addressing
    const uint32_t a_row = (uint32_t)(lane & 15);          // 0..15
    const uint32_t a_half = (uint32_t)(lane >> 4);         // 0/1 -> k byte-half
    const uint32_t b_row8 = (uint32_t)(lane & 7);          // row within 8x8
    const uint32_t b_khalf = (uint32_t)((lane >> 3) & 1);  // k 8-element half
    const uint32_t b_tsel = (uint32_t)(lane >> 4);         // which n-tile of the pair

#pragma unroll 4
    for (int ck = 0; ck < NCHUNK; ck++) {
        // chunk ck's load is complete once <=1 newer group is outstanding.
        // wait BEFORE the barrier: every thread's copies for stage ck are done,
        // then the barrier publishes them CTA-wide (cp.async visibility contract).
        if (ck < NCHUNK - 1) cp_wait<1>(); else cp_wait<0>();
        __syncthreads();
        // Stage (ck+2)%3 == (ck-1)%3 has no readers past this barrier -> refill
        // now so the load overlaps this chunk's MMAs.
        const int nk = ck + 2;
        if (nk < NCHUNK) {
            load_stage(sb + (uint32_t)(nk % NSTAGE) * STAGE_BYTES,
                       aBase + (size_t)nk * A_BLK,
                       bBase + (size_t)nk * B_BLK, tid);
            cp_commit();
        }

        const uint32_t sA = sb + (uint32_t)(ck % NSTAGE) * STAGE_BYTES;
        const uint32_t sB = sA + A_BLK;

#pragma unroll
        for (int ks = 0; ks < 4; ks++) {
            const uint32_t kb = (uint32_t)ks * 32u;        // 16 k-elems = 32 bytes
            // A fragments: 2 m-tiles of 16x16
            uint32_t a[2][4];
#pragma unroll
            for (int mt = 0; mt < 2; mt++) {
                uint32_t off = (uint32_t)(m_warp + mt * 16 + a_row) * 128u + kb + a_half * 16u;
                ldsm_x4(a[mt][0], a[mt][1], a[mt][2], a[mt][3], sA + swz(off));
            }
            // B fragments: n-major rows -> NON-trans ldmatrix; one x4 covers
            // n-tiles (2p,2p+1) x k-halves.
            uint32_t b[8][2];
#pragma unroll
            for (int p = 0; p < 4; p++) {
                uint32_t nrow = (uint32_t)n_warp + (uint32_t)p * 16u + b_tsel * 8u + b_row8;
                uint32_t off = nrow * 128u + kb + b_khalf * 16u;
                uint32_t r0, r1, r2, r3;
                ldsm_x4(r0, r1, r2, r3, sB + swz(off));
                b[p * 2 + 0][0] = r0; b[p * 2 + 0][1] = r1;
                b[p * 2 + 1][0] = r2; b[p * 2 + 1][1] = r3;
            }
#pragma unroll
            for (int mt = 0; mt < 2; mt++)
#pragma unroll
                for (int nt = 0; nt < 8; nt++)
                    mma16816(acc[mt][nt][0], acc[mt][nt][1], acc[mt][nt][2], acc[mt][nt][3],
                             a[mt][0], a[mt][1], a[mt][2], a[mt][3],
                             b[nt][0], b[nt][1]);
        }
        // no trailing barrier: next iteration's barrier provides the ordering
    }

    // ---------------- fused LSTM epilogue (smem-staged, coalesced) ----------------
    __syncthreads();   // all stage reads done before smem is repurposed
    float* gsm = reinterpret_cast<float*>(smem);
    {
        // Phase 1: acc -> smem gate matrix [128][EPI_STRIDE].
        // D frag: d0,d1 = row lane/4 cols 2q,2q+1; d2,d3 = row+8 (q = lane%4).
        const int q2 = (lane & 3) * 2;
        const int lr = lane >> 2;
#pragma unroll
        for (int mt = 0; mt < 2; mt++) {
            const int r0 = m_warp + mt * 16 + lr;
#pragma unroll
            for (int nt = 0; nt < 8; nt++) {
                const int cb = n_warp + nt * 8 + q2;
                *reinterpret_cast<float2*>(&gsm[r0 * EPI_STRIDE + cb]) =
                    make_float2(acc[mt][nt][0], acc[mt][nt][1]);
                *reinterpret_cast<float2*>(&gsm[(r0 + 8) * EPI_STRIDE + cb]) =
                    make_float2(acc[mt][nt][2], acc[mt][nt][3]);
            }
        }
    }

    // cprev prefetch: acc registers are dead after phase-1 staging, so cpv[16]
    // fits without spilling; the 16 independent LDGs fly during the barrier join.
    const int jg = tile_n * 32 + lane;
    float cpv[16];
#pragma unroll
    for (int rr = 0; rr < 16; rr++) {
        const int row = tile_m * TILE_M + warp * 16 + rr;
        cpv[rr] = cprev[(size_t)row * HID_N + jg];
    }

    __syncthreads();

    {
        // Phase 2: warp handles 16 rows; lane covers one j (32 j per CTA).
        // gates (i,f,g,o) adjacent in packed col dim -> one float4 per (row, j).
        const float4 bias = *reinterpret_cast<const float4*>(&g_bias[jg * 4]);
#pragma unroll
        for (int rr = 0; rr < 16; rr++) {
            const int rl = warp * 16 + rr;
            const int row = tile_m * TILE_M + rl;
            float4 gate = *reinterpret_cast<const float4*>(&gsm[rl * EPI_STRIDE + lane * 4]);
            float gi = fast_sigmoid(gate.x + bias.x);
            float gf = fast_sigmoid(gate.y + bias.y);
            float gg = fast_tanh(gate.z + bias.z);
            float go = fast_sigmoid(gate.w + bias.w);
            float cn = gf * cpv[rr] + gi * gg;
            float hn = go * fast_tanh(cn);
            out[(size_t)row * HID_N + jg] = hn;
            out[GATE_ELEMS + (size_t)row * HID_N + jg] = cn;
        }
    }
}

// ---------------------------------------------------------------- launch

extern "C" void kernel_launch(void* const* d_in, const int* in_sizes, int n_in,
                              void* d_out, int out_size)
{
    const float* input = (const float*)d_in[0];
    const float* h     = (const float*)d_in[1];
    const float* c     = (const float*)d_in[2];

    LstmPtrs P;
    P.wi[0] = (const float*)d_in[3];  P.bi[0] = (const float*)d_in[4];
    P.wh[0] = (const float*)d_in[5];  P.bh[0] = (const float*)d_in[6];
    P.wi[1] = (const float*)d_in[7];  P.bi[1] = (const float*)d_in[8];
    P.wh[1] = (const float*)d_in[9];  P.bh[1] = (const float*)d_in[10];
    P.wi[2] = (const float*)d_in[11]; P.bi[2] = (const float*)d_in[12];
    P.wh[2] = (const float*)d_in[13]; P.bh[2] = (const float*)d_in[14];
    P.wi[3] = (const float*)d_in[15]; P.bi[3] = (const float*)d_in[16];
    P.wh[3] = (const float*)d_in[17]; P.bh[3] = (const float*)d_in[18];

    float* out = (float*)d_out;

    // A: 1,048,576 units, 2 per thread -> 2048 blocks
    pack_a_kernel<<<2048, 256>>>(input, h);
    // B: 1,048,576 units, 2 per thread -> 2048 blocks
    pack_b_kernel<<<2048, 256>>>(P);

    cudaFuncSetAttribute(lstm_mma_kernel,
                         cudaFuncAttributeMaxDynamicSharedMemorySize, SMEM_TOTAL);
    dim3 grid(NT_N, NT_M);     // (32, 32)
    lstm_mma_kernel<<<grid, 256, SMEM_TOTAL>>>(c, out);
}